// round 7
// baseline (speedup 1.0000x reference)
#include <cuda_runtime.h>
#include <cuda_bf16.h>
#include <math.h>
#include <cstdint>

// Problem constants
#define BATCH 2
#define SEQ 2048
#define DM 1024
#define NH 16
#define DH 64
#define MROWS (BATCH * SEQ)   // 4096

// ---------------------------------------------------------------------------
// Scratch (no cudaMalloc allowed)
// ---------------------------------------------------------------------------
__device__ float g_Q[MROWS * DM];
__device__ float g_K[MROWS * DM];
__device__ float g_V[MROWS * DM];
__device__ float g_C[MROWS * DM];

// ---------------------------------------------------------------------------
// Common helpers
// ---------------------------------------------------------------------------
__device__ __forceinline__ void mma_tf32(float& c0, float& c1, float& c2, float& c3,
                                         uint32_t a0, uint32_t a1, uint32_t a2, uint32_t a3,
                                         uint32_t b0, uint32_t b1) {
    asm volatile(
        "mma.sync.aligned.m16n8k8.row.col.f32.tf32.tf32.f32 "
        "{%0,%1,%2,%3}, {%4,%5,%6,%7}, {%8,%9}, {%0,%1,%2,%3};"
        : "+f"(c0), "+f"(c1), "+f"(c2), "+f"(c3)
        : "r"(a0), "r"(a1), "r"(a2), "r"(a3), "r"(b0), "r"(b1));
}

// fp32 -> tf32 round-to-nearest bit trick (HW truncates; +0x1000 completes RN)
__device__ __forceinline__ uint32_t rnd_tf32(uint32_t x) { return x + 0x1000u; }
__device__ __forceinline__ uint32_t rnd_tf32f(float x) { return __float_as_uint(x) + 0x1000u; }

__device__ __forceinline__ float ex2f(float x) {
    float y;
    asm("ex2.approx.f32 %0, %1;" : "=f"(y) : "f"(x));
    return y;
}

// ---------------------------------------------------------------------------
// tf32 mma.sync GEMM: C[M,N] = A[M,K] * W[N,K]^T + bias[N]
// Tile 128x128x32, 256 threads. Double-buffered smem, ONE barrier per chunk.
// ---------------------------------------------------------------------------
#define BM 128
#define BN 128
#define BK 32
#define KPAD 36
#define NCHUNK (DM / BK)
#define ABUFU (BM * KPAD)                 // u32 per A (or B) buffer
#define GEMM_SMEM_BYTES (4 * ABUFU * 4)   // 2 A bufs + 2 B bufs

__global__ __launch_bounds__(256, 2) void gemm_tf32_kernel(
    const float* __restrict__ A, const float* __restrict__ W,
    const float* __restrict__ bias, float* __restrict__ C)
{
    extern __shared__ uint32_t gsm[];
    uint32_t* As0 = gsm;                 // [2][BM*KPAD]
    uint32_t* Bs0 = gsm + 2 * ABUFU;     // [2][BN*KPAD]

    const int tid = threadIdx.x;
    const int wid = tid >> 5;
    const int lane = tid & 31;
    const int gid = lane >> 2;
    const int tig = lane & 3;

    const int wm = wid >> 2;
    const int wn = wid & 3;

    const int m0 = blockIdx.y * BM;
    const int n0 = blockIdx.x * BN;

    const int grow = tid >> 3;
    const int gcol = (tid & 7) * 4;

    const uint4* Ag = (const uint4*)(A + (long)(m0 + grow) * DM + gcol);
    const uint4* Wg = (const uint4*)(W + (long)(n0 + grow) * DM + gcol);

    float acc[4][4][4];
    #pragma unroll
    for (int i = 0; i < 4; i++)
        #pragma unroll
        for (int j = 0; j < 4; j++)
            #pragma unroll
            for (int c = 0; c < 4; c++) acc[i][j][c] = 0.0f;

    uint4 ra[4], rb[4];
    #pragma unroll
    for (int i = 0; i < 4; i++) {
        ra[i] = Ag[(long)i * 32 * (DM / 4)];
        rb[i] = Wg[(long)i * 32 * (DM / 4)];
    }
    // store chunk 0 into buffer 0
    #pragma unroll
    for (int i = 0; i < 4; i++) {
        uint4 va = make_uint4(rnd_tf32(ra[i].x), rnd_tf32(ra[i].y),
                              rnd_tf32(ra[i].z), rnd_tf32(ra[i].w));
        *(uint4*)&As0[(grow + i * 32) * KPAD + gcol] = va;
        uint4 vb = make_uint4(rnd_tf32(rb[i].x), rnd_tf32(rb[i].y),
                              rnd_tf32(rb[i].z), rnd_tf32(rb[i].w));
        *(uint4*)&Bs0[(grow + i * 32) * KPAD + gcol] = vb;
    }
    __syncthreads();

    for (int c = 0; c < NCHUNK; c++) {
        const uint32_t* As = As0 + (c & 1) * ABUFU;
        const uint32_t* Bs = Bs0 + (c & 1) * ABUFU;

        // prefetch next chunk into registers (overlaps with MMA below)
        if (c + 1 < NCHUNK) {
            const uint4* an = Ag + (long)(c + 1) * (BK / 4);
            const uint4* bn = Wg + (long)(c + 1) * (BK / 4);
            #pragma unroll
            for (int i = 0; i < 4; i++) {
                ra[i] = an[(long)i * 32 * (DM / 4)];
                rb[i] = bn[(long)i * 32 * (DM / 4)];
            }
        }

        #pragma unroll
        for (int ks = 0; ks < 4; ks++) {
            const int k0 = ks * 8;
            uint32_t af[4][4], bf[4][2];
            #pragma unroll
            for (int mt = 0; mt < 4; mt++) {
                const int r = wm * 64 + mt * 16 + gid;
                af[mt][0] = As[r * KPAD + k0 + tig];
                af[mt][1] = As[(r + 8) * KPAD + k0 + tig];
                af[mt][2] = As[r * KPAD + k0 + tig + 4];
                af[mt][3] = As[(r + 8) * KPAD + k0 + tig + 4];
            }
            #pragma unroll
            for (int nt = 0; nt < 4; nt++) {
                const int r = wn * 32 + nt * 8 + gid;
                bf[nt][0] = Bs[r * KPAD + k0 + tig];
                bf[nt][1] = Bs[r * KPAD + k0 + tig + 4];
            }
            #pragma unroll
            for (int mt = 0; mt < 4; mt++)
                #pragma unroll
                for (int nt = 0; nt < 4; nt++)
                    mma_tf32(acc[mt][nt][0], acc[mt][nt][1],
                             acc[mt][nt][2], acc[mt][nt][3],
                             af[mt][0], af[mt][1], af[mt][2], af[mt][3],
                             bf[nt][0], bf[nt][1]);
        }

        // store prefetched chunk into the other buffer
        if (c + 1 < NCHUNK) {
            uint32_t* An = As0 + ((c + 1) & 1) * ABUFU;
            uint32_t* Bn = Bs0 + ((c + 1) & 1) * ABUFU;
            #pragma unroll
            for (int i = 0; i < 4; i++) {
                uint4 va = make_uint4(rnd_tf32(ra[i].x), rnd_tf32(ra[i].y),
                                      rnd_tf32(ra[i].z), rnd_tf32(ra[i].w));
                *(uint4*)&An[(grow + i * 32) * KPAD + gcol] = va;
                uint4 vb = make_uint4(rnd_tf32(rb[i].x), rnd_tf32(rb[i].y),
                                      rnd_tf32(rb[i].z), rnd_tf32(rb[i].w));
                *(uint4*)&Bn[(grow + i * 32) * KPAD + gcol] = vb;
            }
        }
        __syncthreads();
    }

    #pragma unroll
    for (int mt = 0; mt < 4; mt++) {
        const int mrow = m0 + wm * 64 + mt * 16 + gid;
        #pragma unroll
        for (int nt = 0; nt < 4; nt++) {
            const int ncol = n0 + wn * 32 + nt * 8 + tig * 2;
            const float bx = bias[ncol];
            const float by = bias[ncol + 1];
            float2 v0 = make_float2(acc[mt][nt][0] + bx, acc[mt][nt][1] + by);
            float2 v1 = make_float2(acc[mt][nt][2] + bx, acc[mt][nt][3] + by);
            *(float2*)(C + (long)mrow * DM + ncol) = v0;
            *(float2*)(C + (long)(mrow + 8) * DM + ncol) = v1;
        }
    }
}

// ---------------------------------------------------------------------------
// Tensor-core flash attention, double-buffered K/V, ONE barrier per tile.
// CTA: 128 q-rows (8 warps x 16), key tiles of 64. 256 threads.
// Smem: Ps[128][68] (Q staging + P roundtrip),
//       2 x { Ks[64][68], Vt[64][68] } double buffer.
// Tile staging: thread t handles key = t&63.
//   K: dh = (t>>6)*16 + 4j, LDG.128 -> STS.128 (quad-bank = lane mod 8, CF)
//   V: dh = (t>>6)*4 + 16j, LDG.128 -> 4 scalar transposed STS (bank = lane+c, CF)
// ---------------------------------------------------------------------------
#define APAD 68
#define TILEU (64 * APAD)
#define ATT_SMEM_U32 (128 * APAD + 4 * TILEU)
#define ATT_SMEM_BYTES (ATT_SMEM_U32 * 4)

__global__ __launch_bounds__(256, 2) void attn_mma_kernel(
    const float* __restrict__ Q, const float* __restrict__ K,
    const float* __restrict__ V, float* __restrict__ Ctx)
{
    extern __shared__ uint32_t sm[];
    uint32_t* Ps  = sm;                   // [128][APAD]
    uint32_t* KV0 = sm + 128 * APAD;      // 2 x (Ks + Vt)

    const int bh = blockIdx.y;
    const int b  = bh >> 4;
    const int h  = bh & 15;
    const int q0 = blockIdx.x * 128;

    const int tid  = threadIdx.x;
    const int wid  = tid >> 5;
    const int lane = tid & 31;
    const int gid  = lane >> 2;
    const int tig  = lane & 3;
    const int r0   = wid * 16 + gid;

    const float* Qg = Q + ((long)b * SEQ) * DM + h * DH;
    const float* Kg = K + ((long)b * SEQ) * DM + h * DH;
    const float* Vg = V + ((long)b * SEQ) * DM + h * DH;

    // tile staging coordinates
    const int tkey = tid & 63;
    const int kdhb = (tid >> 6) * 16;   // K: dh = kdhb + 4j
    const int vdhb = (tid >> 6) * 4;    // V: dh = vdhb + 16j

    const float cf = 0.125f * 1.44269504088896f;   // 1/sqrt(64) * log2(e)

    // ---- stage Q (scaled into log2 domain) into Ps
    {
        const int row  = tid >> 1;
        const int col0 = (tid & 1) * 32;
        const float4* qp = (const float4*)(Qg + (long)(q0 + row) * DM + col0);
        #pragma unroll
        for (int j = 0; j < 8; j++) {
            float4 v = qp[j];
            uint32_t* d = &Ps[row * APAD + col0 + j * 4];
            d[0] = rnd_tf32f(v.x * cf);
            d[1] = rnd_tf32f(v.y * cf);
            d[2] = rnd_tf32f(v.z * cf);
            d[3] = rnd_tf32f(v.w * cf);
        }
    }

    // ---- prologue: load K/V tile 0 and store into buffer 0
    float4 kst[4], vst[4];
    {
        const float4* kp = (const float4*)(Kg + (long)tkey * DM + kdhb);
        const float*  vp = Vg + (long)tkey * DM + vdhb;
        #pragma unroll
        for (int j = 0; j < 4; j++) {
            kst[j] = kp[j];
            vst[j] = *(const float4*)(vp + 16 * j);
        }
    }
    {
        uint32_t* Ks = KV0;
        uint32_t* Vt = KV0 + TILEU;
        #pragma unroll
        for (int j = 0; j < 4; j++) {
            uint4 w = make_uint4(rnd_tf32f(kst[j].x), rnd_tf32f(kst[j].y),
                                 rnd_tf32f(kst[j].z), rnd_tf32f(kst[j].w));
            *(uint4*)&Ks[tkey * APAD + kdhb + 4 * j] = w;
            const int dv = vdhb + 16 * j;
            Vt[(dv + 0) * APAD + tkey] = rnd_tf32f(vst[j].x);
            Vt[(dv + 1) * APAD + tkey] = rnd_tf32f(vst[j].y);
            Vt[(dv + 2) * APAD + tkey] = rnd_tf32f(vst[j].z);
            Vt[(dv + 3) * APAD + tkey] = rnd_tf32f(vst[j].w);
        }
    }
    __syncthreads();

    // ---- Q fragments (persistent)
    uint32_t qf[8][4];
    #pragma unroll
    for (int ks = 0; ks < 8; ks++) {
        qf[ks][0] = Ps[r0 * APAD + ks * 8 + tig];
        qf[ks][1] = Ps[(r0 + 8) * APAD + ks * 8 + tig];
        qf[ks][2] = Ps[r0 * APAD + ks * 8 + tig + 4];
        qf[ks][3] = Ps[(r0 + 8) * APAD + ks * 8 + tig + 4];
    }

    float o[8][4];
    #pragma unroll
    for (int nt = 0; nt < 8; nt++)
        #pragma unroll
        for (int c = 0; c < 4; c++) o[nt][c] = 0.0f;
    float mr0 = -INFINITY, mr1 = -INFINITY, l0 = 0.0f, l1 = 0.0f;

    const int NT = SEQ / 64;
    for (int it = 0; it < NT; it++) {
        const uint32_t* Ks = KV0 + (it & 1) * (2 * TILEU);
        const uint32_t* Vt = Ks + TILEU;

        // S = Q * K^T  (per warp: 16 x 64)
        float s[8][4];
        #pragma unroll
        for (int nt = 0; nt < 8; nt++)
            #pragma unroll
            for (int c = 0; c < 4; c++) s[nt][c] = 0.0f;

        #pragma unroll
        for (int nt = 0; nt < 8; nt++) {
            const uint32_t* kb = &Ks[(nt * 8 + gid) * APAD];
            #pragma unroll
            for (int ks = 0; ks < 8; ks++) {
                uint32_t b0 = kb[ks * 8 + tig];
                uint32_t b1 = kb[ks * 8 + tig + 4];
                mma_tf32(s[nt][0], s[nt][1], s[nt][2], s[nt][3],
                         qf[ks][0], qf[ks][1], qf[ks][2], qf[ks][3], b0, b1);
            }
        }

        // online softmax (log2 domain)
        float mt0 = -INFINITY, mt1 = -INFINITY;
        #pragma unroll
        for (int nt = 0; nt < 8; nt++) {
            mt0 = fmaxf(mt0, fmaxf(s[nt][0], s[nt][1]));
            mt1 = fmaxf(mt1, fmaxf(s[nt][2], s[nt][3]));
        }
        mt0 = fmaxf(mt0, __shfl_xor_sync(0xffffffffu, mt0, 1));
        mt0 = fmaxf(mt0, __shfl_xor_sync(0xffffffffu, mt0, 2));
        mt1 = fmaxf(mt1, __shfl_xor_sync(0xffffffffu, mt1, 1));
        mt1 = fmaxf(mt1, __shfl_xor_sync(0xffffffffu, mt1, 2));

        const float mn0 = fmaxf(mr0, mt0);
        const float mn1 = fmaxf(mr1, mt1);
        const float a0 = ex2f(mr0 - mn0);
        const float a1 = ex2f(mr1 - mn1);
        mr0 = mn0; mr1 = mn1;

        float rs0 = 0.0f, rs1 = 0.0f;
        #pragma unroll
        for (int nt = 0; nt < 8; nt++) {
            float p0 = ex2f(s[nt][0] - mn0);
            float p1 = ex2f(s[nt][1] - mn0);
            float p2 = ex2f(s[nt][2] - mn1);
            float p3 = ex2f(s[nt][3] - mn1);
            rs0 += p0 + p1;
            rs1 += p2 + p3;
            uint2 w0 = make_uint2(rnd_tf32f(p0), rnd_tf32f(p1));
            uint2 w1 = make_uint2(rnd_tf32f(p2), rnd_tf32f(p3));
            *(uint2*)&Ps[r0 * APAD + nt * 8 + tig * 2] = w0;
            *(uint2*)&Ps[(r0 + 8) * APAD + nt * 8 + tig * 2] = w1;
        }
        rs0 += __shfl_xor_sync(0xffffffffu, rs0, 1);
        rs0 += __shfl_xor_sync(0xffffffffu, rs0, 2);
        rs1 += __shfl_xor_sync(0xffffffffu, rs1, 1);
        rs1 += __shfl_xor_sync(0xffffffffu, rs1, 2);

        l0 = l0 * a0 + rs0;
        l1 = l1 * a1 + rs1;
        #pragma unroll
        for (int nt = 0; nt < 8; nt++) {
            o[nt][0] *= a0; o[nt][1] *= a0;
            o[nt][2] *= a1; o[nt][3] *= a1;
        }
        __syncwarp();   // P stores visible to all lanes of this warp

        // prefetch next K/V tile into registers (hides under PV)
        if (it + 1 < NT) {
            const long kr = (long)((it + 1) * 64 + tkey);
            const float4* kp = (const float4*)(Kg + kr * DM + kdhb);
            const float*  vp = Vg + kr * DM + vdhb;
            #pragma unroll
            for (int j = 0; j < 4; j++) {
                kst[j] = kp[j];
                vst[j] = *(const float4*)(vp + 16 * j);
            }
        }

        // O += P * V
        #pragma unroll
        for (int ks = 0; ks < 8; ks++) {
            uint32_t pa0 = Ps[r0 * APAD + ks * 8 + tig];
            uint32_t pa1 = Ps[(r0 + 8) * APAD + ks * 8 + tig];
            uint32_t pa2 = Ps[r0 * APAD + ks * 8 + tig + 4];
            uint32_t pa3 = Ps[(r0 + 8) * APAD + ks * 8 + tig + 4];
            #pragma unroll
            for (int nt = 0; nt < 8; nt++) {
                const uint32_t* vb = &Vt[(nt * 8 + gid) * APAD];
                uint32_t b0 = vb[ks * 8 + tig];
                uint32_t b1 = vb[ks * 8 + tig + 4];
                mma_tf32(o[nt][0], o[nt][1], o[nt][2], o[nt][3],
                         pa0, pa1, pa2, pa3, b0, b1);
            }
        }

        // store prefetched tile into the other buffer
        if (it + 1 < NT) {
            uint32_t* nKs = KV0 + ((it + 1) & 1) * (2 * TILEU);
            uint32_t* nVt = nKs + TILEU;
            #pragma unroll
            for (int j = 0; j < 4; j++) {
                uint4 w = make_uint4(rnd_tf32f(kst[j].x), rnd_tf32f(kst[j].y),
                                     rnd_tf32f(kst[j].z), rnd_tf32f(kst[j].w));
                *(uint4*)&nKs[tkey * APAD + kdhb + 4 * j] = w;
                const int dv = vdhb + 16 * j;
                nVt[(dv + 0) * APAD + tkey] = rnd_tf32f(vst[j].x);
                nVt[(dv + 1) * APAD + tkey] = rnd_tf32f(vst[j].y);
                nVt[(dv + 2) * APAD + tkey] = rnd_tf32f(vst[j].z);
                nVt[(dv + 3) * APAD + tkey] = rnd_tf32f(vst[j].w);
            }
        }
        __syncthreads();
    }

    // epilogue: normalize and write context
    const float inv0 = 1.0f / l0;
    const float inv1 = 1.0f / l1;
    float* C0 = Ctx + ((long)b * SEQ + q0 + r0) * DM + h * DH;
    float* C1 = Ctx + ((long)b * SEQ + q0 + r0 + 8) * DM + h * DH;
    #pragma unroll
    for (int nt = 0; nt < 8; nt++) {
        const int col = nt * 8 + tig * 2;
        *(float2*)(C0 + col) = make_float2(o[nt][0] * inv0, o[nt][1] * inv0);
        *(float2*)(C1 + col) = make_float2(o[nt][2] * inv1, o[nt][3] * inv1);
    }
}

// ---------------------------------------------------------------------------
// kernel_launch  — inputs: q,k,v, Wq,bq, Wk,bk, Wv,bv, Wo,bo
// ---------------------------------------------------------------------------
extern "C" void kernel_launch(void* const* d_in, const int* in_sizes, int n_in,
                              void* d_out, int out_size)
{
    const float* q  = (const float*)d_in[0];
    const float* k  = (const float*)d_in[1];
    const float* v  = (const float*)d_in[2];
    const float* Wq = (const float*)d_in[3];
    const float* bq = (const float*)d_in[4];
    const float* Wk = (const float*)d_in[5];
    const float* bk = (const float*)d_in[6];
    const float* Wv = (const float*)d_in[7];
    const float* bv = (const float*)d_in[8];
    const float* Wo = (const float*)d_in[9];
    const float* bo = (const float*)d_in[10];
    float* out = (float*)d_out;

    float *pQ, *pK, *pV, *pC;
    cudaGetSymbolAddress((void**)&pQ, g_Q);
    cudaGetSymbolAddress((void**)&pK, g_K);
    cudaGetSymbolAddress((void**)&pV, g_V);
    cudaGetSymbolAddress((void**)&pC, g_C);

    cudaFuncSetAttribute(gemm_tf32_kernel,
                         cudaFuncAttributeMaxDynamicSharedMemorySize,
                         GEMM_SMEM_BYTES);
    cudaFuncSetAttribute(attn_mma_kernel,
                         cudaFuncAttributeMaxDynamicSharedMemorySize,
                         ATT_SMEM_BYTES);

    dim3 ggrid(DM / BN, MROWS / BM);     // (8, 32)
    gemm_tf32_kernel<<<ggrid, 256, GEMM_SMEM_BYTES>>>(q, Wq, bq, pQ);
    gemm_tf32_kernel<<<ggrid, 256, GEMM_SMEM_BYTES>>>(k, Wk, bk, pK);
    gemm_tf32_kernel<<<ggrid, 256, GEMM_SMEM_BYTES>>>(v, Wv, bv, pV);

    dim3 agrid(SEQ / 128, BATCH * NH);   // (16, 32)
    attn_mma_kernel<<<agrid, 256, ATT_SMEM_BYTES>>>(pQ, pK, pV, pC);

    gemm_tf32_kernel<<<ggrid, 256, GEMM_SMEM_BYTES>>>(pC, Wo, bo, out);
}